// round 17
// baseline (speedup 1.0000x reference)
#include <cuda_runtime.h>

#define FULL 0xffffffffu
typedef unsigned int u32;

constexpr int L = 16;
constexpr int RING = 8;
constexpr float LOG2E = 1.4426950408889634f;
constexpr float LN2   = 0.6931471805599453f;

__device__ __forceinline__ float ex2f(float v) {
    float r; asm("ex2.approx.f32 %0,%1;" : "=f"(r) : "f"(v)); return r;
}
__device__ __forceinline__ u32 pkbf(float hi, float lo) {
    u32 r; asm("cvt.rn.bf16x2.f32 %0,%1,%2;" : "=r"(r) : "f"(hi), "f"(lo)); return r;
}
// ALU-only bf16x2 pack (round-to-nearest ties-up; inputs always positive finite)
__device__ __forceinline__ u32 pkrnd(float hi, float lo) {
    u32 a = __float_as_uint(lo) + 0x8000u;
    u32 b = __float_as_uint(hi) + 0x8000u;
    u32 r; asm("prmt.b32 %0,%1,%2,0x7632;" : "=r"(r) : "r"(a), "r"(b));
    return r;
}
__device__ __forceinline__ u32 mulbf2(u32 a, u32 b) {
    u32 r; asm("mul.rn.bf16x2 %0,%1,%2;" : "=r"(r) : "r"(a), "r"(b)); return r;
}
__device__ __forceinline__ float bflo(u32 v) { return __uint_as_float(v << 16); }
__device__ __forceinline__ float bfhi(u32 v) { return __uint_as_float(v & 0xffff0000u); }

__device__ __forceinline__ void mma16816(
    float& d0, float& d1, float& d2, float& d3,
    u32 a0, u32 a1, u32 a2, u32 a3, u32 b0, u32 b1)
{
    asm volatile(
        "mma.sync.aligned.m16n8k16.row.col.f32.bf16.bf16.f32 "
        "{%0,%1,%2,%3}, {%4,%5,%6,%7}, {%8,%9}, {%10,%11,%12,%13};"
        : "=f"(d0), "=f"(d1), "=f"(d2), "=f"(d3)
        : "r"(a0), "r"(a1), "r"(a2), "r"(a3), "r"(b0), "r"(b1),
          "f"(0.f), "f"(0.f), "f"(0.f), "f"(0.f));
}

// state permutation on the MMA k/n axes
__host__ __device__ __forceinline__ int sigma(int i) {
    return (i < 8) ? ((i & 1) ? 2 * i - 1 : 2 * i)
                   : ((i & 1) ? 2 * i - 15 : 2 * i - 14);
}

// Grid = 128 blocks x 32 batches. Block = 256 threads = 8 warps:
//  w0-3: DUAL-chain recursion warps — fwd AND bwd of the same 8 batches,
//        explicitly interleaved in one instruction stream (4 independent
//        MMAs in flight per step-pair; combine is warp-local).
//  w4-7: emit + transition scores.
// One dual warp per SMSP across the full chip.
__global__ __launch_bounds__(256, 1) void crf_kernel(
    const float* __restrict__ x, const float* __restrict__ trans,
    const int* __restrict__ label, const int* __restrict__ length,
    float* __restrict__ out, int B, int T)
{
    __shared__ float sE[L * L];
    __shared__ float sT[L * L];
    __shared__ float sScore[32];

    int tid  = threadIdx.x;
    int lane = tid & 31;
    int w    = tid >> 5;
    int g    = lane >> 2;     // batch row 0..7
    int tig  = lane & 3;

    if (tid < L * L) {
        float tv = trans[tid];
        sT[tid] = tv;
        sE[tid] = tv * LOG2E;
    }
    __syncthreads();

    int blockBase = blockIdx.x * 32;

    if (w < 4) {
        int b = blockBase + w * 8 + g;
        int len = length[b];
        int m = (len - 1) >> 1;
        int cntF = m;
        int cntW = max(len - 2 - m, 0);
        int clF = max(cntF - 1, 0), clW = max(cntW - 1, 0);

        int kMax = max(cntF, cntW);
#pragma unroll
        for (int o = 4; o <= 16; o <<= 1)
            kMax = max(kMax, __shfl_xor_sync(FULL, kMax, o));
        int kMaxPad = (kMax + RING - 1) & ~(RING - 1);

        // B fragments, fwd (F) and bwd (W = transposed) orientations
        u32 b00F, b01F, b10F, b11F, b00W, b01W, b10W, b11W;
        {
            int r0 = 4 * tig;
            int cA = sigma(g);
            int cB = sigma(g + 8);
            b00F = pkbf(ex2f(sE[(r0 + 1) * L + cA]), ex2f(sE[r0 * L + cA]));
            b01F = pkbf(ex2f(sE[(r0 + 3) * L + cA]), ex2f(sE[(r0 + 2) * L + cA]));
            b10F = pkbf(ex2f(sE[(r0 + 1) * L + cB]), ex2f(sE[r0 * L + cB]));
            b11F = pkbf(ex2f(sE[(r0 + 3) * L + cB]), ex2f(sE[(r0 + 2) * L + cB]));
            b00W = pkbf(ex2f(sE[cA * L + r0 + 1]), ex2f(sE[cA * L + r0]));
            b01W = pkbf(ex2f(sE[cA * L + r0 + 3]), ex2f(sE[cA * L + r0 + 2]));
            b10W = pkbf(ex2f(sE[cB * L + r0 + 1]), ex2f(sE[cB * L + r0]));
            b11W = pkbf(ex2f(sE[cB * L + r0 + 3]), ex2f(sE[cB * L + r0 + 2]));
        }

        const float* p = x + (size_t)b * T * L + tig * 4;

        // init: fwd from row 0, bwd from row len-1
        float4 iF = *(const float4*)(p);
        float4 iW = *(const float4*)(p + (size_t)(len - 1) * L);
        u32 A0F = pkbf(ex2f(iF.y * LOG2E), ex2f(iF.x * LOG2E));
        u32 A2F = pkbf(ex2f(iF.w * LOG2E), ex2f(iF.z * LOG2E));
        u32 A0W = pkbf(ex2f(iW.y * LOG2E), ex2f(iW.x * LOG2E));
        u32 A2W = pkbf(ex2f(iW.w * LOG2E), ex2f(iW.z * LOG2E));
        int MsF = 0, MsW = 0;

        // prefetch rings (clamped)
        float4 rF[RING], rW[RING];
#pragma unroll
        for (int d = 0; d < RING; ++d) {
            rF[d] = *(const float4*)(p + (size_t)(1 + min(d, clF)) * L);
            rW[d] = *(const float4*)(p + (size_t)max(len - 2 - min(d, clW), 0) * L);
        }

        for (int k0 = 0; k0 < kMaxPad; k0 += RING) {
#pragma unroll
            for (int kk = 0; kk < RING; ++kk) {
                int k = k0 + kk;

                // 4 independent MMAs (2 per chain) back-to-back
                float dF0, dF1, dF2, dF3, fF0, fF1, fF2, fF3;
                float dW0, dW1, dW2, dW3, fW0, fW1, fW2, fW3;
                mma16816(dF0, dF1, dF2, dF3, A0F, A0F, A2F, A2F, b00F, b01F);
                mma16816(fF0, fF1, fF2, fF3, A0F, A0F, A2F, A2F, b10F, b11F);
                mma16816(dW0, dW1, dW2, dW3, A0W, A0W, A2W, A2W, b00W, b01W);
                mma16816(fW0, fW1, fW2, fW3, A0W, A0W, A2W, A2W, b10W, b11W);

                // exps + packs, both chains — overlaps MMA latency
                float4 xF = rF[kk], xW = rW[kk];
                float eF0 = ex2f(xF.x * LOG2E), eF1 = ex2f(xF.y * LOG2E);
                float eF2 = ex2f(xF.z * LOG2E), eF3 = ex2f(xF.w * LOG2E);
                float eW0 = ex2f(xW.x * LOG2E), eW1 = ex2f(xW.y * LOG2E);
                float eW2 = ex2f(xW.z * LOG2E), eW3 = ex2f(xW.w * LOG2E);
                u32 ePF0 = pkrnd(eF1, eF0), ePF2 = pkrnd(eF3, eF2);
                u32 ePW0 = pkrnd(eW1, eW0), ePW2 = pkrnd(eW3, eW2);

                // ring refills
                rF[kk] = *(const float4*)(p + (size_t)(1 + min(k + RING, clF)) * L);
                rW[kk] = *(const float4*)(p + (size_t)max(len - 2 - min(k + RING, clW), 0) * L);

                // tails
                u32 n0F = mulbf2(pkrnd(dF1, dF0), ePF0);
                u32 n2F = mulbf2(pkrnd(fF1, fF0), ePF2);
                u32 n0W = mulbf2(pkrnd(dW1, dW0), ePW0);
                u32 n2W = mulbf2(pkrnd(fW1, fW0), ePW2);

                bool aF = k < cntF, aW = k < cntW;
                A0F = aF ? n0F : A0F;  A2F = aF ? n2F : A2F;
                A0W = aW ? n0W : A0W;  A2W = aW ? n2W : A2W;

                if (kk == RING - 1) {   // exponent-only rescale, both chains
                    u32 s0F = __shfl_sync(FULL, A0F, lane & ~3);
                    u32 s0W = __shfl_sync(FULL, A0W, lane & ~3);
                    int eeF = (int)((s0F >> 7) & 0xff) - 127;
                    int eeW = (int)((s0W >> 7) & 0xff) - 127;
                    u32 hF = (u32)(127 - eeF) << 7;
                    u32 hW = (u32)(127 - eeW) << 7;
                    u32 scF = aF ? (hF | (hF << 16)) : 0x3f803f80u;
                    u32 scW = aW ? (hW | (hW << 16)) : 0x3f803f80u;
                    MsF += aF ? eeF : 0;
                    MsW += aW ? eeW : 0;
                    A0F = mulbf2(A0F, scF); A2F = mulbf2(A2F, scF);
                    A0W = mulbf2(A0W, scW); A2W = mulbf2(A2W, scW);
                }
            }
        }

        // bwd final plain matvec: beta_m = E * q~
        float dW0, dW1, dW2, dW3, fW0, fW1, fW2, fW3;
        mma16816(dW0, dW1, dW2, dW3, A0W, A0W, A2W, A2W, b00W, b01W);
        mma16816(fW0, fW1, fW2, fW3, A0W, A0W, A2W, A2W, b10W, b11W);
        if (len == 1) { dW0 = dW1 = 1.f; fW0 = fW1 = 1.f; }

        __syncthreads();   // emit scores ready

        // warp-local combine: z = log(s_F . beta) + (MsF+MsW)*ln2
        float pr = dW0 * bflo(A0F) + dW1 * bfhi(A0F)
                 + fW0 * bflo(A2F) + fW1 * bfhi(A2F);
        pr += __shfl_xor_sync(FULL, pr, 1);
        pr += __shfl_xor_sync(FULL, pr, 2);
        float z = __logf(pr) + (float)(MsF + MsW) * LN2;
        if (tig == 0) out[b] = z - sScore[w * 8 + g];
    } else {
        // ---------------- emit / transition warps ----------------
        int we = w - 4;
#pragma unroll 1
        for (int k2 = 0; k2 < 8; ++k2) {
            int sl = we * 8 + k2;
            int bb = blockBase + sl;
            const int*   lb = label + (size_t)bb * T;
            const float* xb = x + (size_t)bb * T * L;
            int ll = length[bb];

            float acc = 0.f;
            for (int t = lane; t < ll; t += 32) {
                int lab = lb[t];
                acc += __ldg(xb + t * L + lab);
                if (t >= 1) acc += sT[lb[t - 1] * L + lab];
            }
            acc += __shfl_xor_sync(FULL, acc, 16);
            acc += __shfl_xor_sync(FULL, acc, 8);
            acc += __shfl_xor_sync(FULL, acc, 4);
            acc += __shfl_xor_sync(FULL, acc, 2);
            acc += __shfl_xor_sync(FULL, acc, 1);
            if (lane == 0) sScore[sl] = acc;
        }
        __syncthreads();
    }
}

extern "C" void kernel_launch(void* const* d_in, const int* in_sizes, int n_in,
                              void* d_out, int out_size) {
    const float* x      = (const float*)d_in[0];
    const float* trans  = (const float*)d_in[1];
    const int*   label  = (const int*)d_in[2];
    const int*   length = (const int*)d_in[3];
    float*       out    = (float*)d_out;

    int B = in_sizes[3];                 // 4096
    int T = in_sizes[2] / B;             // 512

    int grid = (B + 31) / 32;            // 32 batches per block, 128 blocks
    crf_kernel<<<grid, 256>>>(x, trans, label, length, out, B, T);
}